// round 3
// baseline (speedup 1.0000x reference)
#include <cuda_runtime.h>
#include <math.h>

#define B_       8
#define N_       1024
#define NCTA     18            // CTAs per batch
#define GRID_    (B_ * NCTA)   // 144 <= 148 SMs -> all co-resident at 1 CTA/SM
#define ROWS_MAX 57            // ceil(1024/18)
#define ROWS_SM  55            // rows held in shared memory (55*4KB = 225,280 B)
#define NREG     8             // first NREG rows also cached in registers (pass A)
#define ITERS    100
#define RINV     (1.0f / 1024.0f)
#define LMB      10.0f

// Partial buffers for w = K^T u (single-buffered: barrier ordering makes reuse safe)
__device__ float        g_part[B_][NCTA][N_];
// Reduced z vector per batch
__device__ float        g_z[B_][N_];
// Monotonic per-batch barrier counters (reset by init kernel each launch)
__device__ unsigned int g_bar[B_];

__global__ void rt_init() {
    if (threadIdx.x < B_) g_bar[threadIdx.x] = 0u;
}

__device__ __forceinline__ float wred(float x) {
    x += __shfl_xor_sync(0xffffffffu, x, 16);
    x += __shfl_xor_sync(0xffffffffu, x, 8);
    x += __shfl_xor_sync(0xffffffffu, x, 4);
    x += __shfl_xor_sync(0xffffffffu, x, 2);
    x += __shfl_xor_sync(0xffffffffu, x, 1);
    return x;
}

// Per-batch multi-CTA barrier: release -> arrive -> spin -> acquire.
__device__ __forceinline__ void batch_barrier(int b, int tid, unsigned int* gen) {
    (*gen)++;
    __syncthreads();
    if (tid == 0) {
        __threadfence();
        atomicAdd(&g_bar[b], 1u);
        const unsigned int tgt = (*gen) * NCTA;
        volatile unsigned int* bp = &g_bar[b];
        while (*bp < tgt) { __nanosleep(20); }
        __threadfence();
    }
    __syncthreads();
}

__global__ void __launch_bounds__(1024, 1)
rt_kernel(const float* __restrict__ Mn, float* __restrict__ out) {
    extern __shared__ float sm[];
    float* Ks    = sm;                    // [ROWS_SM * N_]
    float* z_s   = sm + ROWS_SM * N_;     // [N_]
    float* u_s   = z_s + N_;              // [64]  (rows 0..54 SMEM rows, 55/56 reg rows)
    float* red_s = u_s + 64;              // [64]

    const int tid  = threadIdx.x;
    const int lane = tid & 31;
    const int warp = tid >> 5;
    const int b    = blockIdx.x / NCTA;
    const int pid  = blockIdx.x % NCTA;
    const int row0 = pid * ROWS_MAX;
    const int nrows = min(ROWS_MAX, N_ - row0);  // 57, except last CTA: 55
    const int nreg  = nrows - ROWS_SM;           // 2 or 0

    const float* Mb = Mn + (size_t)b * N_ * N_;

    // ---- Build K = exp(-lambda * min(M, 5)) : 55 rows SMEM, 2 rows regs ----
    float kr0 = 0.f, kr1 = 0.f;
    float Kreg[NREG];
    for (int li = 0; li < nrows; li++) {
        float m = Mb[(size_t)(row0 + li) * N_ + tid];
        float k = expf(-LMB * fminf(m, 5.0f));
        if (li < ROWS_SM)       Ks[li * N_ + tid] = k;
        else if (li == ROWS_SM) kr0 = k;
        else                    kr1 = k;
        if (li < NREG) Kreg[li] = k;
    }
    if (tid < 64) u_s[tid] = (tid < nrows) ? RINV : 0.f;
    __syncthreads();

    unsigned int gen = 0;
    float v = 0.f;

    // Columns this CTA reduces in phase 2 of the allreduce
    const int mycol = pid * ROWS_MAX + tid;       // thread t -> column, t < ROWS_MAX
    const bool redthr = (tid < ROWS_MAX) && (mycol < N_);

    for (int iter = 0; iter <= ITERS; iter++) {
        // ---- Pass A: w[j] = sum_i K[i][j] * u[i]  (column-parallel) ----
        float w;
        {
            const float4* u4 = (const float4*)u_s;
            float4 uu = u4[0];
            w  = Kreg[0]*uu.x + Kreg[1]*uu.y + Kreg[2]*uu.z + Kreg[3]*uu.w;
            uu = u4[1];
            w += Kreg[4]*uu.x + Kreg[5]*uu.y + Kreg[6]*uu.z + Kreg[7]*uu.w;
            #pragma unroll
            for (int q = 2; q < 13; q++) {
                float4 u2 = u4[q];
                const int r = q << 2;
                w += Ks[(r+0)*N_+tid]*u2.x + Ks[(r+1)*N_+tid]*u2.y
                   + Ks[(r+2)*N_+tid]*u2.z + Ks[(r+3)*N_+tid]*u2.w;
            }
            float4 ut = u4[13];  // rows 52,53,54,(55=kr0)
            w += Ks[52*N_+tid]*ut.x + Ks[53*N_+tid]*ut.y + Ks[54*N_+tid]*ut.z
               + kr0*ut.w + kr1*u_s[56];
        }
        __stcg(&g_part[b][pid][tid], w);

        batch_barrier(b, tid, &gen);   // barrier A: all partials visible

        // ---- Phase 2: this CTA reduces its own column slice -> z slice ----
        if (redthr) {
            float a = 0.f;
            #pragma unroll
            for (int q = 0; q < NCTA; q++)
                a += __ldcg(&g_part[b][q][mycol]);
            __stcg(&g_z[b][mycol], RINV / a);
        }

        batch_barrier(b, tid, &gen);   // barrier B: full z visible

        const float z = __ldcg(&g_z[b][tid]);
        z_s[tid] = z;
        __syncthreads();

        if (iter == ITERS) { v = z; break; }   // final pass gives v = c/(K^T u)

        // ---- Pass B: t[i] = sum_j K[i][j] z[j]; u[i] = r / t[i] ----
        if (warp < 14) {
            const int rb = warp << 2;
            const int r1 = min(rb + 1, ROWS_SM - 1);
            const int r2 = min(rb + 2, ROWS_SM - 1);
            const int r3 = min(rb + 3, ROWS_SM - 1);
            float t0 = 0.f, t1 = 0.f, t2 = 0.f, t3 = 0.f;
            #pragma unroll 4
            for (int k = 0; k < 32; k++) {
                const int c = lane + (k << 5);
                const float zv = z_s[c];
                t0 += Ks[rb * N_ + c] * zv;
                t1 += Ks[r1 * N_ + c] * zv;
                t2 += Ks[r2 * N_ + c] * zv;
                t3 += Ks[r3 * N_ + c] * zv;
            }
            t0 = wred(t0); t1 = wred(t1); t2 = wred(t2); t3 = wred(t3);
            if (lane == 0) {
                u_s[rb] = RINV / t0;
                if (rb + 1 < ROWS_SM) u_s[rb + 1] = RINV / t1;
                if (rb + 2 < ROWS_SM) u_s[rb + 2] = RINV / t2;
                if (rb + 3 < ROWS_SM) u_s[rb + 3] = RINV / t3;
            }
        }
        // Register-resident overflow rows (rows 55,56 of this CTA): block reduce
        float p0 = wred(kr0 * z);
        float p1 = wred(kr1 * z);
        if (lane == 0) { red_s[warp] = p0; red_s[32 + warp] = p1; }
        __syncthreads();
        if (warp == 0) {
            float s0 = wred(red_s[lane]);
            float s1 = wred(red_s[32 + lane]);
            if (lane == 0 && nreg > 0) {
                u_s[ROWS_SM]     = RINV / s0;
                u_s[ROWS_SM + 1] = RINV / s1;
            }
        }
        __syncthreads();   // u_s ready for next pass A
    }

    // ---- Write P[i][j] = u[i] * K[i][j] * v[j] ----
    float* outb = out + (size_t)b * N_ * N_;
    for (int li = 0; li < ROWS_SM; li++) {
        outb[(size_t)(row0 + li) * N_ + tid] = u_s[li] * Ks[li * N_ + tid] * v;
    }
    if (nreg > 0) {
        outb[(size_t)(row0 + ROWS_SM)     * N_ + tid] = u_s[ROWS_SM]     * kr0 * v;
        outb[(size_t)(row0 + ROWS_SM + 1) * N_ + tid] = u_s[ROWS_SM + 1] * kr1 * v;
    }
}

extern "C" void kernel_launch(void* const* d_in, const int* in_sizes, int n_in,
                              void* d_out, int out_size) {
    const float* M = (const float*)d_in[0];
    float* out = (float*)d_out;

    const int smem_bytes = (ROWS_SM * N_ + N_ + 64 + 64) * (int)sizeof(float); // 229,888 B
    static bool attr_set = false;
    if (!attr_set) {
        cudaFuncSetAttribute(rt_kernel, cudaFuncAttributeMaxDynamicSharedMemorySize, smem_bytes);
        attr_set = true;
    }

    rt_init<<<1, 32>>>();
    rt_kernel<<<GRID_, 1024, smem_bytes>>>(M, out);
}

// round 6
// speedup vs baseline: 1.6039x; 1.6039x over previous
#include <cuda_runtime.h>
#include <cuda_fp16.h>
#include <math.h>

#define B_       8
#define N_       1024
#define NP_      512           // column pairs
#define NCTA     18            // CTAs per batch
#define GRID_    (B_ * NCTA)   // 144 <= 148 SMs -> all co-resident at 1 CTA/SM
#define ROWS_MAX 57            // ceil(1024/18)
#define NRP      8             // rows 0..7 of each column-pair cached in registers
#define ITERS    100
#define RINV     (1.0f / 1024.0f)
#define LMB      10.0f

// Ping-ponged half2 partials (ping-pong needed: only one barrier per iteration)
__device__ __half2      g_ph[2][B_][NCTA][NP_];
// fp32 partials for the final (v-producing) pass
__device__ float2       g_pf[B_][NCTA][NP_];
// Monotonic per-batch barrier counters (reset each launch)
__device__ unsigned int g_bar[B_];

__global__ void rt_init() {
    if (threadIdx.x < B_) g_bar[threadIdx.x] = 0u;
}

__device__ __forceinline__ float wred(float x) {
    x += __shfl_xor_sync(0xffffffffu, x, 16);
    x += __shfl_xor_sync(0xffffffffu, x, 8);
    x += __shfl_xor_sync(0xffffffffu, x, 4);
    x += __shfl_xor_sync(0xffffffffu, x, 2);
    x += __shfl_xor_sync(0xffffffffu, x, 1);
    return x;
}

// Per-batch multi-CTA barrier: release -> arrive -> spin -> acquire.
__device__ __forceinline__ void batch_barrier(int b, int tid, unsigned int* gen) {
    (*gen)++;
    __syncthreads();
    if (tid == 0) {
        __threadfence();
        atomicAdd(&g_bar[b], 1u);
        const unsigned int tgt = (*gen) * NCTA;
        volatile unsigned int* bp = &g_bar[b];
        while (*bp < tgt) { __nanosleep(20); }
        __threadfence();
    }
    __syncthreads();
}

__global__ void __launch_bounds__(1024, 1)
rt_kernel(const float* __restrict__ Mn, float* __restrict__ out) {
    extern __shared__ float sm[];
    float*   z_s  = sm;                        // [1024] (float2-aligned)
    float*   u_s  = sm + N_;                   // [64]
    __half*  Ksh  = (__half*)(sm + N_ + 64);   // [ROWS_MAX * 1024] halves
    __half2* Ks2  = (__half2*)Ksh;             // [ROWS_MAX * 512]  pairs

    const int tid  = threadIdx.x;
    const int lane = tid & 31;
    const int warp = tid >> 5;
    const int b    = blockIdx.x / NCTA;
    const int pid  = blockIdx.x % NCTA;
    const int row0 = pid * ROWS_MAX;
    const int nrows = min(ROWS_MAX, N_ - row0);  // 57, last CTA: 55

    const float* Mb = Mn + (size_t)b * N_ * N_;

    // ---- Build K = exp(-lambda*min(M,5)) in fp16 SMEM (column tid of each row) ----
    for (int li = 0; li < ROWS_MAX; li++) {
        float k = 0.f;
        if (li < nrows) {
            float m = Mb[(size_t)(row0 + li) * N_ + tid];
            k = expf(-LMB * fminf(m, 5.0f));
        }
        Ksh[li * N_ + tid] = __float2half_rn(k);   // zero rows beyond nrows
    }
    if (tid < 64) u_s[tid] = (tid < nrows) ? RINV : 0.f;
    __syncthreads();

    // Register cache: rows 0..NRP-1 of this thread's column pair (t < 512)
    __half2 Kreg[NRP];
    if (tid < NP_) {
        #pragma unroll
        for (int li = 0; li < NRP; li++) Kreg[li] = Ks2[li * NP_ + tid];
    }

    unsigned int gen = 0;
    const float4* U4 = (const float4*)u_s;

    for (int iter = 0; iter <= ITERS; iter++) {
        // ---- Pass A: w[j] = sum_i K[i][j]*u[i], thread t owns columns 2t,2t+1 ----
        const int buf = iter & 1;
        float w0 = 0.f, w1 = 0.f;
        if (tid < NP_) {
            #pragma unroll
            for (int q = 0; q < 14; q++) {       // rows 0..55
                const float4 uu = U4[q];
                const int r = q << 2;
                float2 k0, k1, k2, k3;
                if (q < 2) {
                    k0 = __half22float2(Kreg[r + 0]);
                    k1 = __half22float2(Kreg[r + 1]);
                    k2 = __half22float2(Kreg[r + 2]);
                    k3 = __half22float2(Kreg[r + 3]);
                } else {
                    k0 = __half22float2(Ks2[(r + 0) * NP_ + tid]);
                    k1 = __half22float2(Ks2[(r + 1) * NP_ + tid]);
                    k2 = __half22float2(Ks2[(r + 2) * NP_ + tid]);
                    k3 = __half22float2(Ks2[(r + 3) * NP_ + tid]);
                }
                w0 += k0.x*uu.x + k1.x*uu.y + k2.x*uu.z + k3.x*uu.w;
                w1 += k0.y*uu.x + k1.y*uu.y + k2.y*uu.z + k3.y*uu.w;
            }
            {   // row 56
                const float u56 = u_s[56];
                const float2 k = __half22float2(Ks2[56 * NP_ + tid]);
                w0 += k.x * u56;
                w1 += k.y * u56;
            }
            if (iter < ITERS) __stcg(&g_ph[buf][b][pid][tid], __floats2half2_rn(w0, w1));
            else              __stcg(&g_pf[b][pid][tid], make_float2(w0, w1));
        }

        batch_barrier(b, tid, &gen);   // all partials visible

        // ---- Reduce partials -> z pair, publish to SMEM ----
        if (tid < NP_) {
            float a0 = 0.f, a1 = 0.f;
            if (iter < ITERS) {
                #pragma unroll
                for (int q = 0; q < NCTA; q++) {
                    const float2 p = __half22float2(__ldcg(&g_ph[buf][b][q][tid]));
                    a0 += p.x; a1 += p.y;
                }
            } else {
                #pragma unroll
                for (int q = 0; q < NCTA; q++) {
                    const float2 p = __ldcg(&g_pf[b][q][tid]);
                    a0 += p.x; a1 += p.y;
                }
            }
            ((float2*)z_s)[tid] = make_float2(RINV / a0, RINV / a1);
        }
        __syncthreads();

        if (iter == ITERS) break;      // z_s now holds v

        // ---- Pass B: t[i] = sum_j K[i][j] z[j]; u[i] = r/t[i] (0 past nrows) ----
        if (warp < 14) {               // rows 4w..4w+3 (0..55)
            const int rb = warp << 2;
            float t0 = 0.f, t1 = 0.f, t2 = 0.f, t3 = 0.f;
            #pragma unroll 4
            for (int k = 0; k < 16; k++) {
                const int c2 = lane + (k << 5);
                const float2 zz = ((const float2*)z_s)[c2];
                const float2 k0 = __half22float2(Ks2[(rb + 0) * NP_ + c2]);
                const float2 k1 = __half22float2(Ks2[(rb + 1) * NP_ + c2]);
                const float2 k2 = __half22float2(Ks2[(rb + 2) * NP_ + c2]);
                const float2 k3 = __half22float2(Ks2[(rb + 3) * NP_ + c2]);
                t0 += k0.x*zz.x + k0.y*zz.y;
                t1 += k1.x*zz.x + k1.y*zz.y;
                t2 += k2.x*zz.x + k2.y*zz.y;
                t3 += k3.x*zz.x + k3.y*zz.y;
            }
            t0 = wred(t0); t1 = wred(t1); t2 = wred(t2); t3 = wred(t3);
            if (lane == 0) {
                u_s[rb + 0] = (rb + 0 < nrows) ? RINV / t0 : 0.f;
                u_s[rb + 1] = (rb + 1 < nrows) ? RINV / t1 : 0.f;
                u_s[rb + 2] = (rb + 2 < nrows) ? RINV / t2 : 0.f;
                u_s[rb + 3] = (rb + 3 < nrows) ? RINV / t3 : 0.f;
            }
        } else if (warp == 14) {       // row 56
            float t56 = 0.f;
            #pragma unroll 4
            for (int k = 0; k < 16; k++) {
                const int c2 = lane + (k << 5);
                const float2 zz = ((const float2*)z_s)[c2];
                const float2 kk = __half22float2(Ks2[56 * NP_ + c2]);
                t56 += kk.x*zz.x + kk.y*zz.y;
            }
            t56 = wred(t56);
            if (lane == 0) u_s[56] = (56 < nrows) ? RINV / t56 : 0.f;
        }
        __syncthreads();               // u_s ready for next pass A
    }

    // ---- Epilogue: P[i][j] = u[i] * K32[i][j] * v[j], K recomputed in fp32 ----
    const float vj = z_s[tid];         // v for column tid
    float* outb = out + (size_t)b * N_ * N_;
    #pragma unroll 4
    for (int li = 0; li < nrows; li++) {
        const float m = Mb[(size_t)(row0 + li) * N_ + tid];
        const float k = expf(-LMB * fminf(m, 5.0f));
        outb[(size_t)(row0 + li) * N_ + tid] = u_s[li] * k * vj;
    }
}

extern "C" void kernel_launch(void* const* d_in, const int* in_sizes, int n_in,
                              void* d_out, int out_size) {
    const float* M = (const float*)d_in[0];
    float* out = (float*)d_out;

    // z(4KB) + u(256B) + K fp16 (57*1024*2 = 116736B)
    const int smem_bytes = (N_ + 64) * (int)sizeof(float) + ROWS_MAX * N_ * (int)sizeof(__half);
    static bool attr_set = false;
    if (!attr_set) {
        cudaFuncSetAttribute(rt_kernel, cudaFuncAttributeMaxDynamicSharedMemorySize, smem_bytes);
        attr_set = true;
    }

    rt_init<<<1, 32>>>();
    rt_kernel<<<GRID_, 1024, smem_bytes>>>(M, out);
}